// round 3
// baseline (speedup 1.0000x reference)
#include <cuda_runtime.h>

// ---------------------------------------------------------------------------
// Problem constants
// ---------------------------------------------------------------------------
#define BB 4
#define TT 16
#define HH 64
#define WW 64
#define FF 64
#define CN 256            // 4*F gate channels
#define HW (HH*WW)        // 4096
#define HW3 (32*32)       // 1024

// Scratch (device globals: allocation-free rule)
__device__ float g_xz[(long long)BB*TT*HW*CN];   // 67,108,864 floats (256 MiB)
__device__ float g_z [(long long)BB*HW*CN];      // 4,194,304
__device__ float g_ha[(long long)BB*TT*HW*FF];   // 16,777,216
__device__ float g_h3[(long long)BB*TT*HW3*FF];  // 4,194,304
__device__ float g_c [(long long)BB*HW*FF];      // 1,048,576

typedef unsigned long long u64;

__device__ __forceinline__ u64 splat2(float a) {
    u64 r;
    asm("mov.b64 %0, {%1, %1};" : "=l"(r) : "r"(__float_as_uint(a)));
    return r;
}
__device__ __forceinline__ void ffma2(u64& acc, u64 a, u64 b) {
    asm("fma.rn.f32x2 %0, %1, %2, %0;" : "+l"(acc) : "l"(a), "l"(b));
}

// ---------------------------------------------------------------------------
// Implicit-GEMM conv kernel.
//   A: im2col gather of input  (M = n_img*Ho*Wo, K = KH*KH*Cin)
//   B: weights (K x 256) row-major  (exactly the (kh,kw,Cin,4F) layout)
//   C: out[img, p, n] (+ optional bias[n], + optional addend[img,p,n])
// Optional BN on the gathered input: v*(bns[ci]/sqrt(1.001)) + bnb[ci]
// Tiling: BM=128, BN=128, BK=16, 256 threads, 8x8 per thread, f32x2 FMAs.
// Requirements satisfied by this problem: M%128==0, Kdim%16==0, Cin%8==0.
// ---------------------------------------------------------------------------
#define BM 128
#define BNT 128
#define BK 16

template<int KH, int STRIDE>
__global__ void __launch_bounds__(256)
conv_gemm(const float* __restrict__ in, long long in_img_stride,
          const float* __restrict__ wgt,
          const float* __restrict__ bias,
          const float* __restrict__ bns, const float* __restrict__ bnb,
          const float* __restrict__ addend, long long add_img_stride,
          float* __restrict__ out, long long out_img_stride,
          int Hin, int Win, int Cin, int Ho, int Wo, int Kdim)
{
    constexpr int PAD = (KH - 1) / 2;
    const float BN_RS = 0.9995003746877732f;   // 1/sqrt(1+1e-3)

    __shared__ float As[BK][BM];
    __shared__ float Bs[BK][BNT];

    const int tid  = threadIdx.x;
    const int tx   = tid & 15;     // n subtile
    const int ty   = tid >> 4;     // m subtile
    const int nblk = blockIdx.x * BNT;
    const int mblk = blockIdx.y * BM;
    const int HoWo = Ho * Wo;

    // A-load mapping: row a_m, k range [a_k, a_k+8)
    const int a_m = tid & 127;
    const int a_k = (tid >> 7) * 8;
    {
        // nothing
    }
    const int m_g  = mblk + a_m;
    const int img_a = m_g / HoWo;
    const int p_a   = m_g - img_a * HoWo;
    const int oy    = p_a / Wo;
    const int ox    = p_a - oy * Wo;

    // B-load mapping
    const int b_k = tid >> 4;          // 0..15
    const int b_n = (tid & 15) * 8;    // 0..120

    u64 acc[8][4];
    #pragma unroll
    for (int i = 0; i < 8; i++)
        #pragma unroll
        for (int j = 0; j < 4; j++) acc[i][j] = 0ull;

    for (int kt = 0; kt < Kdim; kt += BK) {
        // ---- load A tile (implicit im2col gather) ----
        {
            const int kg = kt + a_k;
            const int ci = kg % Cin;          // kg multiple of 8, Cin multiple of 8
            const int r  = kg / Cin;
            const int kx = r % KH;
            const int ky = r / KH;
            const int iy = oy * STRIDE + ky - PAD;
            const int ix = ox * STRIDE + kx - PAD;
            const bool valid = ((unsigned)iy < (unsigned)Hin) &&
                               ((unsigned)ix < (unsigned)Win);
            float av[8];
            if (valid) {
                const float4* src = reinterpret_cast<const float4*>(
                    in + (long long)img_a * in_img_stride +
                    ((long long)iy * Win + ix) * Cin + ci);
                float4 v0 = src[0];
                float4 v1 = src[1];
                av[0]=v0.x; av[1]=v0.y; av[2]=v0.z; av[3]=v0.w;
                av[4]=v1.x; av[5]=v1.y; av[6]=v1.z; av[7]=v1.w;
                if (bns) {
                    #pragma unroll
                    for (int j = 0; j < 8; j++)
                        av[j] = av[j] * (__ldg(&bns[ci + j]) * BN_RS) + __ldg(&bnb[ci + j]);
                }
            } else {
                #pragma unroll
                for (int j = 0; j < 8; j++) av[j] = 0.f;
            }
            #pragma unroll
            for (int j = 0; j < 8; j++) As[a_k + j][a_m] = av[j];
        }
        // ---- load B tile (weights, contiguous) ----
        {
            const float4* wp = reinterpret_cast<const float4*>(
                wgt + (long long)(kt + b_k) * CN + nblk + b_n);
            *reinterpret_cast<float4*>(&Bs[b_k][b_n])     = wp[0];
            *reinterpret_cast<float4*>(&Bs[b_k][b_n + 4]) = wp[1];
        }
        __syncthreads();

        // ---- compute ----
        #pragma unroll
        for (int k = 0; k < BK; k++) {
            float4 a0 = *reinterpret_cast<const float4*>(&As[k][ty * 8]);
            float4 a1 = *reinterpret_cast<const float4*>(&As[k][ty * 8 + 4]);
            ulonglong2 b01 = *reinterpret_cast<const ulonglong2*>(&Bs[k][tx * 8]);
            ulonglong2 b23 = *reinterpret_cast<const ulonglong2*>(&Bs[k][tx * 8 + 4]);
            u64 bb[4] = { b01.x, b01.y, b23.x, b23.y };
            float aa[8] = { a0.x, a0.y, a0.z, a0.w, a1.x, a1.y, a1.z, a1.w };
            #pragma unroll
            for (int i = 0; i < 8; i++) {
                u64 as = splat2(aa[i]);
                #pragma unroll
                for (int j = 0; j < 4; j++) ffma2(acc[i][j], as, bb[j]);
            }
        }
        __syncthreads();
    }

    // ---- epilogue ----
    #pragma unroll
    for (int i = 0; i < 8; i++) {
        const int m   = mblk + ty * 8 + i;
        const int img = m / HoWo;
        const int p   = m - img * HoWo;
        const int ng  = nblk + tx * 8;
        float v[8];
        #pragma unroll
        for (int j = 0; j < 4; j++) {
            float2 f = *reinterpret_cast<float2*>(&acc[i][j]);
            v[2 * j] = f.x; v[2 * j + 1] = f.y;
        }
        if (bias) {
            #pragma unroll
            for (int j = 0; j < 8; j++) v[j] += __ldg(&bias[ng + j]);
        }
        if (addend) {
            const float4* ap = reinterpret_cast<const float4*>(
                addend + (long long)img * add_img_stride + (long long)p * CN + ng);
            float4 q0 = ap[0], q1 = ap[1];
            v[0]+=q0.x; v[1]+=q0.y; v[2]+=q0.z; v[3]+=q0.w;
            v[4]+=q1.x; v[5]+=q1.y; v[6]+=q1.z; v[7]+=q1.w;
        }
        float* op = out + (long long)img * out_img_stride + (long long)p * CN + ng;
        *reinterpret_cast<float4*>(op)     = make_float4(v[0], v[1], v[2], v[3]);
        *reinterpret_cast<float4*>(op + 4) = make_float4(v[4], v[5], v[6], v[7]);
    }
}

// ---------------------------------------------------------------------------
// LSTM gate kernel: z (img,pix,256) -> c,h   (hard-sigmoid gates, relu cell)
// ---------------------------------------------------------------------------
__device__ __forceinline__ float hsg(float x) {
    return fminf(fmaxf(fmaf(x, 0.2f, 0.5f), 0.f), 1.f);
}

__global__ void gate_kernel(const float* __restrict__ z, long long z_img_stride,
                            float* __restrict__ c,
                            float* __restrict__ hout, long long h_img_stride,
                            int HWp, int n_img, int first)
{
    const int idx = blockIdx.x * blockDim.x + threadIdx.x;
    const int total = n_img * HWp * (FF / 4);
    if (idx >= total) return;
    const int f4  = idx & 15;        // FF/4 == 16
    const int pp  = idx >> 4;
    const int pix = pp % HWp;
    const int img = pp / HWp;

    const float* zb = z + (long long)img * z_img_stride + (long long)pix * CN + f4 * 4;
    float4 zi = *reinterpret_cast<const float4*>(zb);
    float4 zf = *reinterpret_cast<const float4*>(zb + FF);
    float4 zc = *reinterpret_cast<const float4*>(zb + 2 * FF);
    float4 zo = *reinterpret_cast<const float4*>(zb + 3 * FF);

    const long long coff = ((long long)img * HWp + pix) * FF + f4 * 4;
    float4 cold = first ? make_float4(0.f, 0.f, 0.f, 0.f)
                        : *reinterpret_cast<const float4*>(c + coff);

    float4 cn, hh;
    cn.x = hsg(zf.x) * cold.x + hsg(zi.x) * fmaxf(zc.x, 0.f);
    cn.y = hsg(zf.y) * cold.y + hsg(zi.y) * fmaxf(zc.y, 0.f);
    cn.z = hsg(zf.z) * cold.z + hsg(zi.z) * fmaxf(zc.z, 0.f);
    cn.w = hsg(zf.w) * cold.w + hsg(zi.w) * fmaxf(zc.w, 0.f);
    hh.x = hsg(zo.x) * fmaxf(cn.x, 0.f);
    hh.y = hsg(zo.y) * fmaxf(cn.y, 0.f);
    hh.z = hsg(zo.z) * fmaxf(cn.z, 0.f);
    hh.w = hsg(zo.w) * fmaxf(cn.w, 0.f);

    *reinterpret_cast<float4*>(c + coff) = cn;
    float* hb = hout + (long long)img * h_img_stride + (long long)pix * FF + f4 * 4;
    *reinterpret_cast<float4*>(hb) = hh;
}

// ---------------------------------------------------------------------------
// Conv3D 3x3x3, 64 -> 1, 'SAME', + ReLU.  h3: (B,T,32,32,64), out: (B,T,32,32)
// ---------------------------------------------------------------------------
__global__ void conv3d_kernel(const float* __restrict__ h,
                              const float* __restrict__ w,
                              const float* __restrict__ b,
                              float* __restrict__ out)
{
    const int idx = blockIdx.x * blockDim.x + threadIdx.x;
    if (idx >= BB * TT * 32 * 32) return;
    const int x  = idx & 31;
    const int y  = (idx >> 5) & 31;
    const int t  = (idx >> 10) & 15;
    const int bb = idx >> 14;

    float acc = __ldg(&b[0]);
    #pragma unroll
    for (int dt = -1; dt <= 1; dt++) {
        const int ti = t + dt;
        if ((unsigned)ti >= (unsigned)TT) continue;
        #pragma unroll
        for (int dy = -1; dy <= 1; dy++) {
            const int yi = y + dy;
            if ((unsigned)yi >= 32u) continue;
            #pragma unroll
            for (int dx = -1; dx <= 1; dx++) {
                const int xi = x + dx;
                if ((unsigned)xi >= 32u) continue;
                const float4* hp = reinterpret_cast<const float4*>(
                    h + ((((long long)bb * TT + ti) * 32 + yi) * 32 + xi) * FF);
                const float4* wp = reinterpret_cast<const float4*>(
                    w + (((dt + 1) * 3 + (dy + 1)) * 3 + (dx + 1)) * FF);
                #pragma unroll
                for (int c4 = 0; c4 < FF / 4; c4++) {
                    float4 hv = hp[c4];
                    float4 wv = __ldg(&wp[c4]);
                    acc += hv.x * wv.x + hv.y * wv.y + hv.z * wv.z + hv.w * wv.w;
                }
            }
        }
    }
    out[idx] = fmaxf(acc, 0.f);
}

// ---------------------------------------------------------------------------
// Host launch helpers
// ---------------------------------------------------------------------------
template<int KH, int STRIDE>
static void conv_launch(const float* in, long long in_str,
                        const float* w, const float* bias,
                        const float* bns, const float* bnb,
                        const float* add, long long add_str,
                        float* out, long long out_str,
                        int Hin, int Win, int Cin, int Ho, int Wo, int n_img)
{
    const int Kdim = KH * KH * Cin;
    const int M = n_img * Ho * Wo;
    dim3 grid(CN / BNT, M / BM);
    conv_gemm<KH, STRIDE><<<grid, 256>>>(in, in_str, w, bias, bns, bnb,
                                         add, add_str, out, out_str,
                                         Hin, Win, Cin, Ho, Wo, Kdim);
}

static void gate_launch(const float* z, long long z_str, float* c,
                        float* hout, long long h_str, int HWp, int n_img, int first)
{
    const int total = n_img * HWp * (FF / 4);
    gate_kernel<<<(total + 255) / 256, 256>>>(z, z_str, c, hout, h_str, HWp, n_img, first);
}

extern "C" void kernel_launch(void* const* d_in, const int* in_sizes, int n_in,
                              void* d_out, int out_size)
{
    const float* x   = (const float*)d_in[0];
    const float* k1  = (const float*)d_in[1];
    const float* rk1 = (const float*)d_in[2];
    const float* b1  = (const float*)d_in[3];
    const float* g1  = (const float*)d_in[4];
    const float* be1 = (const float*)d_in[5];
    const float* k2  = (const float*)d_in[6];
    const float* rk2 = (const float*)d_in[7];
    const float* b2  = (const float*)d_in[8];
    const float* g2  = (const float*)d_in[9];
    const float* be2 = (const float*)d_in[10];
    const float* k3  = (const float*)d_in[11];
    const float* rk3 = (const float*)d_in[12];
    const float* b3  = (const float*)d_in[13];
    const float* w3d = (const float*)d_in[14];
    const float* b3d = (const float*)d_in[15];
    float* out = (float*)d_out;

    float *xz, *zb, *ha, *h3, *cc;
    cudaGetSymbolAddress((void**)&xz, g_xz);
    cudaGetSymbolAddress((void**)&zb, g_z);
    cudaGetSymbolAddress((void**)&ha, g_ha);
    cudaGetSymbolAddress((void**)&h3, g_h3);
    cudaGetSymbolAddress((void**)&cc, g_c);

    const long long X_IMG   = (long long)HW * 16;       // input x img stride (Cin=16)
    const long long XZ_IMG  = (long long)TT * HW * CN;   // xz stride over b
    const long long XZ_T    = (long long)HW * CN;        // xz stride over t
    const long long H_IMG   = (long long)TT * HW * FF;   // h stride over b
    const long long H_T     = (long long)HW * FF;        // h stride over t
    const long long Z_IMG   = (long long)HW * CN;
    const long long XZ3_IMG = (long long)TT * HW3 * CN;
    const long long XZ3_T   = (long long)HW3 * CN;
    const long long H3_IMG  = (long long)TT * HW3 * FF;
    const long long H3_T    = (long long)HW3 * FF;
    const long long Z3_IMG  = (long long)HW3 * CN;

    // ================= Layer 1: ConvLSTM 5x5, F=64, stride 1 =================
    // input conv for all (b,t)
    conv_launch<5, 1>(x, X_IMG, k1, b1, nullptr, nullptr, nullptr, 0,
                      xz, XZ_T, HH, WW, 16, HH, WW, BB * TT);
    // t = 0 (h_{-1} = 0)
    gate_launch(xz, XZ_IMG, cc, ha, H_IMG, HW, BB, 1);
    for (int t = 1; t < TT; t++) {
        conv_launch<5, 1>(ha + (long long)(t - 1) * H_T, H_IMG, rk1,
                          nullptr, nullptr, nullptr,
                          xz + (long long)t * XZ_T, XZ_IMG,
                          zb, Z_IMG, HH, WW, FF, HH, WW, BB);
        gate_launch(zb, Z_IMG, cc, ha + (long long)t * H_T, H_IMG, HW, BB, 0);
    }

    // ================= Layer 2: ConvLSTM 3x3, F=64, stride 1 (BN1 on input) ==
    conv_launch<3, 1>(ha, H_T, k2, b2, g1, be1, nullptr, 0,
                      xz, XZ_T, HH, WW, FF, HH, WW, BB * TT);
    gate_launch(xz, XZ_IMG, cc, ha, H_IMG, HW, BB, 1);   // overwrites h1[0] (done with it)
    for (int t = 1; t < TT; t++) {
        conv_launch<3, 1>(ha + (long long)(t - 1) * H_T, H_IMG, rk2,
                          nullptr, nullptr, nullptr,
                          xz + (long long)t * XZ_T, XZ_IMG,
                          zb, Z_IMG, HH, WW, FF, HH, WW, BB);
        gate_launch(zb, Z_IMG, cc, ha + (long long)t * H_T, H_IMG, HW, BB, 0);
    }

    // ================= Layer 3: ConvLSTM 1x1, F=64, stride 2 (BN2 on input) ==
    conv_launch<1, 2>(ha, H_T, k3, b3, g2, be2, nullptr, 0,
                      xz, XZ3_T, HH, WW, FF, 32, 32, BB * TT);
    gate_launch(xz, XZ3_IMG, cc, h3, H3_IMG, HW3, BB, 1);
    for (int t = 1; t < TT; t++) {
        conv_launch<1, 1>(h3 + (long long)(t - 1) * H3_T, H3_IMG, rk3,
                          nullptr, nullptr, nullptr,
                          xz + (long long)t * XZ3_T, XZ3_IMG,
                          zb, Z3_IMG, 32, 32, FF, 32, 32, BB);
        gate_launch(zb, Z3_IMG, cc, h3 + (long long)t * H3_T, H3_IMG, HW3, BB, 0);
    }

    // ================= Conv3D 3x3x3 -> 1 + ReLU ==============================
    conv3d_kernel<<<(BB * TT * 32 * 32 + 255) / 256, 256>>>(h3, w3d, b3d, out);
}

// round 5
// speedup vs baseline: 2.2146x; 2.2146x over previous
#include <cuda_runtime.h>
#include <cuda_bf16.h>

typedef unsigned int u32;
typedef unsigned long long u64;

#define BB 4
#define TT 16
#define HH 64
#define WW 64
#define FF 64
#define HW 4096
#define HW3 1024

// Scratch (device globals: allocation-free rule). xz is stored in the
// gate-interleaved PERMUTED layout: column pcol = feature*4 + gate(i,f,c,o).
__device__ float g_xz[(long long)BB*TT*HW*256];
__device__ float g_ha[(long long)BB*TT*HW*FF];
__device__ float g_h3[(long long)BB*TT*HW3*FF];
__device__ float g_c [(long long)BB*HW*FF];
__device__ u32   g_wb32[843776];   // packed bf16 hi/lo weight fragments
__device__ float g_pb[768];        // permuted biases for 3 layers

__device__ __forceinline__ float hsg(float x){ return fminf(fmaxf(fmaf(x,0.2f,0.5f),0.f),1.f); }
__device__ __forceinline__ u32 smem_u32(const void* p){
    u32 a;
    asm("{ .reg .u64 t; cvta.to.shared.u64 t, %1; cvt.u32.u64 %0, t; }":"=r"(a):"l"(p));
    return a;
}
__device__ __forceinline__ void cpa16(u32 s, const void* g){
    asm volatile("cp.async.cg.shared.global [%0], [%1], 16;"::"r"(s),"l"(g));
}
#define CP_COMMIT() asm volatile("cp.async.commit_group;")
#define CP_WAIT0()  asm volatile("cp.async.wait_group 0;" ::: "memory")
__device__ __forceinline__ void ldm4(u32* r, u32 a){
    asm volatile("ldmatrix.sync.aligned.m8n8.x4.shared.b16 {%0,%1,%2,%3}, [%4];"
        :"=r"(r[0]),"=r"(r[1]),"=r"(r[2]),"=r"(r[3]):"r"(a));
}
__device__ __forceinline__ void mma16816(float* c, const u32* a, u32 b0, u32 b1){
    asm volatile("mma.sync.aligned.m16n8k16.row.col.f32.bf16.bf16.f32 "
        "{%0,%1,%2,%3}, {%4,%5,%6,%7}, {%8,%9}, {%0,%1,%2,%3};"
        : "+f"(c[0]),"+f"(c[1]),"+f"(c[2]),"+f"(c[3])
        : "r"(a[0]),"r"(a[1]),"r"(a[2]),"r"(a[3]),"r"(b0),"r"(b1));
}

// ---------------------------------------------------------------------------
// Weight prep: fp32 (K x 256, cols ordered i|f|c|o x 64) -> per-32k-chunk
// bf16 hi/lo B-fragment images for mma.m16n8k16, with columns PERMUTED to
// pcol = f*4+g. Chunk layout (u32): [hi 4096][lo 4096];
// index = (k16*32 + ntile)*64 + lane*2 + reg.
// ---------------------------------------------------------------------------
__global__ void prep_w(const float* __restrict__ w, u32* __restrict__ dst, int K, int NCP)
{
    int idx = blockIdx.x*256 + threadIdx.x;
    if (idx >= NCP*4096) return;
    int chunk = idx >> 12, r = idx & 4095;
    int k16 = r >> 11, t = r & 2047;
    int nt = t >> 6, u = t & 63;
    int lane = u >> 1, reg = u & 1;
    int pcol = nt*8 + (lane>>2);
    int f = pcol >> 2, g = pcol & 3;
    int n_orig = g*64 + f;
    int kg = chunk*32 + k16*16 + reg*8 + (lane&3)*2;
    float v0 = (kg   < K) ? w[(long long)kg*256 + n_orig] : 0.f;
    float v1 = (kg+1 < K) ? w[(long long)(kg+1)*256 + n_orig] : 0.f;
    __nv_bfloat16 h0 = __float2bfloat16(v0), h1 = __float2bfloat16(v1);
    __nv_bfloat16 l0 = __float2bfloat16(v0 - __bfloat162float(h0));
    __nv_bfloat16 l1 = __float2bfloat16(v1 - __bfloat162float(h1));
    union { __nv_bfloat162 b; u32 x; } ph, pl;
    ph.b = __nv_bfloat162(h0, h1);
    pl.b = __nv_bfloat162(l0, l1);
    dst[(long long)chunk*8192 + r]        = ph.x;
    dst[(long long)chunk*8192 + 4096 + r] = pl.x;
}

__global__ void prep_bias(const float* b1, const float* b2, const float* b3,
                          float* __restrict__ pb)
{
    int i = blockIdx.x*256 + threadIdx.x;
    if (i >= 768) return;
    int l = i >> 8, pcol = i & 255;
    const float* b = (l==0) ? b1 : ((l==1) ? b2 : b3);
    pb[i] = b[(pcol&3)*64 + (pcol>>2)];
}

// ---------------------------------------------------------------------------
// HMMA implicit-GEMM conv. BM=128, BN=256, BK=32, 512 threads (4x4 warps),
// bf16x3 (A_hi*B_hi + A_hi*B_lo + A_lo*B_hi), fp32 accum.
// FUSE=false: out[img,pix,pcol] = conv + biasP (permuted z layout)
// FUSE=true : z = conv + xza; LSTM gate update -> cbuf, outp = h (feature layout)
// Stage layout (53248 B): [A_hi 10240][A_lo 10240][B_hi 16384][B_lo 16384]
// A rows padded to 80 B (32 k bf16 = 64 B + 16 pad) for conflict-free ldmatrix.
// ---------------------------------------------------------------------------
#define STG_BYTES 53248
#define SMEM_TOT  106496

template<int KH, int STRIDE, int CIN, bool HASBN, bool FUSE>
__global__ void __launch_bounds__(512, 1)
conv_mma(const float* __restrict__ in, long long in_str,
         const u32* __restrict__ wch, int NC,
         const float* __restrict__ biasP,
         const float* __restrict__ bns, const float* __restrict__ bnb,
         const float* __restrict__ xza, long long xz_str,
         float* __restrict__ cbuf,
         float* __restrict__ outp, long long out_str,
         int Hin, int Win, int Ho, int Wo)
{
    constexpr int PAD = (KH-1)/2;
    extern __shared__ char smem[];
    const u32 sb = smem_u32(smem);
    const int tid = threadIdx.x, wid = tid>>5, lane = tid&31;
    const int wm = wid>>2, wn = wid&3;
    const int HoWo = Ho*Wo;
    const int mblk = blockIdx.x << 7;

    // A-gather coordinates: thread owns row arow, k-segment kseg (8 k values)
    const int arow = tid & 127, kseg = tid >> 7;
    const int am = mblk + arow;
    const int aimg = am / HoWo;
    const int ap = am - aimg*HoWo;
    const int oy = ap / Wo, ox = ap - (ap/Wo)*Wo;
    const float* inp = in + (long long)aimg*in_str;

    const int ldm_off = ((lane&7) + ((lane>>3)&1)*8)*80 + (lane>>4)*16;

    float acc[2][8][4];
    #pragma unroll
    for (int i=0;i<2;i++)
        #pragma unroll
        for (int j=0;j<8;j++)
            #pragma unroll
            for (int k=0;k<4;k++) acc[i][j][k]=0.f;

    auto gather = [&](int ic, float* v){
        #pragma unroll
        for (int e=0;e<8;e++) v[e]=0.f;
        const int kg = ic*32 + kseg*8;
        const int tap = kg / CIN;
        if (tap < KH*KH){
            const int ci = kg % CIN;
            const int ky = tap / KH, kx = tap - (tap/KH)*KH;
            const int iy = oy*STRIDE + ky - PAD;
            const int ix = ox*STRIDE + kx - PAD;
            if ((unsigned)iy < (unsigned)Hin && (unsigned)ix < (unsigned)Win){
                const float4* sp = (const float4*)(inp + ((long long)iy*Win+ix)*CIN + ci);
                float4 a0 = sp[0], a1 = sp[1];
                v[0]=a0.x; v[1]=a0.y; v[2]=a0.z; v[3]=a0.w;
                v[4]=a1.x; v[5]=a1.y; v[6]=a1.z; v[7]=a1.w;
                if (HASBN){
                    const float BNRS = 0.9995003746877732f;  // 1/sqrt(1+1e-3)
                    #pragma unroll
                    for (int e=0;e<8;e++)
                        v[e] = fmaf(v[e], __ldg(bns+ci+e)*BNRS, __ldg(bnb+ci+e));
                }
            }
        }
    };
    auto storeA = [&](int s, const float* v){
        u32 hw[4], lw[4];
        #pragma unroll
        for (int e=0;e<4;e++){
            __nv_bfloat16 h0=__float2bfloat16(v[2*e]), h1=__float2bfloat16(v[2*e+1]);
            __nv_bfloat16 l0=__float2bfloat16(v[2*e]-__bfloat162float(h0));
            __nv_bfloat16 l1=__float2bfloat16(v[2*e+1]-__bfloat162float(h1));
            union { __nv_bfloat162 b; u32 x; } ph, pl;
            ph.b = __nv_bfloat162(h0,h1); pl.b = __nv_bfloat162(l0,l1);
            hw[e]=ph.x; lw[e]=pl.x;
        }
        char* base = smem + s*STG_BYTES + arow*80 + kseg*16;
        *(uint4*)base           = make_uint4(hw[0],hw[1],hw[2],hw[3]);
        *(uint4*)(base + 10240) = make_uint4(lw[0],lw[1],lw[2],lw[3]);
    };
    auto copyB = [&](int ic, int s){
        const char* src = (const char*)(wch + (long long)ic*8192);
        u32 dstb = sb + s*STG_BYTES + 20480;
        #pragma unroll
        for (int i=0;i<4;i++)
            cpa16(dstb + tid*16 + i*8192, src + tid*16 + i*8192);
        CP_COMMIT();
    };
    auto compute = [&](int s){
        const u32 Ab = sb + s*STG_BYTES;
        const char* Bb = smem + s*STG_BYTES + 20480;
        #pragma unroll
        for (int k16=0;k16<2;k16++){
            u32 ah[2][4], al[2][4];
            #pragma unroll
            for (int mt=0;mt<2;mt++){
                u32 ra = Ab + (wm*32+mt*16)*80 + ldm_off + k16*32;
                ldm4(ah[mt], ra);
                ldm4(al[mt], ra + 10240);
            }
            #pragma unroll
            for (int nt=0;nt<8;nt++){
                int off = ((k16*32 + wn*8 + nt)*64 + lane*2)*4;
                uint2 bh = *(const uint2*)(Bb + off);
                uint2 bl = *(const uint2*)(Bb + 16384 + off);
                #pragma unroll
                for (int mt=0;mt<2;mt++){
                    mma16816(acc[mt][nt], ah[mt], bh.x, bh.y);
                    mma16816(acc[mt][nt], ah[mt], bl.x, bl.y);
                    mma16816(acc[mt][nt], al[mt], bh.x, bh.y);
                }
            }
        }
    };

    float vreg[8];
    copyB(0, 0);
    gather(0, vreg);
    storeA(0, vreg);
    CP_WAIT0();
    __syncthreads();
    for (int ic=0; ic<NC; ic++){
        const int s = ic & 1;
        const bool more = (ic+1 < NC);
        if (more){ copyB(ic+1, s^1); gather(ic+1, vreg); }
        compute(s);
        if (more){ storeA(s^1, vreg); CP_WAIT0(); }
        __syncthreads();
    }

    // ---- epilogue via SMEM (two 64-row halves) ----
    float* zsm = (float*)smem;   // [64][264] fp32
    #pragma unroll
    for (int half=0; half<2; half++){
        if ((wm>>1) == half){
            const int rb = (wm&1)*32;
            #pragma unroll
            for (int mt=0;mt<2;mt++){
                #pragma unroll
                for (int nt=0;nt<8;nt++){
                    int row = rb + mt*16 + (lane>>2);
                    int col = wn*64 + nt*8 + (lane&3)*2;
                    *(float2*)&zsm[row*264 + col]     = make_float2(acc[mt][nt][0], acc[mt][nt][1]);
                    *(float2*)&zsm[(row+8)*264 + col] = make_float2(acc[mt][nt][2], acc[mt][nt][3]);
                }
            }
        }
        __syncthreads();
        {
            const int row = tid >> 3, fg = tid & 7;  // 8 threads/row, 8 features each
            const int m = mblk + half*64 + row;
            const int img = m / HoWo;
            const int pix = m - img*HoWo;
            float4 q[8];
            #pragma unroll
            for (int j=0;j<8;j++) q[j] = *(float4*)&zsm[row*264 + fg*32 + j*4];
            if (FUSE){
                const float* za = xza + (long long)img*xz_str + (long long)pix*256 + fg*32;
                float* cp = cbuf + ((long long)img*HoWo + pix)*64 + fg*8;
                float* hp = outp + (long long)img*out_str + (long long)pix*64 + fg*8;
                float co[8], cn[8], ho[8];
                *(float4*)&co[0] = *(const float4*)cp;
                *(float4*)&co[4] = *(const float4*)(cp+4);
                #pragma unroll
                for (int j=0;j<8;j++){
                    float4 x = *(const float4*)(za + j*4);
                    float zi = q[j].x + x.x, zf = q[j].y + x.y;
                    float zc = q[j].z + x.z, zo = q[j].w + x.w;
                    float c = hsg(zf)*co[j] + hsg(zi)*fmaxf(zc,0.f);
                    cn[j] = c; ho[j] = hsg(zo)*fmaxf(c,0.f);
                }
                *(float4*)cp     = *(float4*)&cn[0];
                *(float4*)(cp+4) = *(float4*)&cn[4];
                *(float4*)hp     = *(float4*)&ho[0];
                *(float4*)(hp+4) = *(float4*)&ho[4];
            } else {
                float* op = outp + (long long)img*out_str + (long long)pix*256 + fg*32;
                #pragma unroll
                for (int j=0;j<8;j++){
                    float4 bv = *(const float4*)(biasP + fg*32 + j*4);
                    *(float4*)(op + j*4) =
                        make_float4(q[j].x+bv.x, q[j].y+bv.y, q[j].z+bv.z, q[j].w+bv.w);
                }
            }
        }
        __syncthreads();
    }
}

// ---------------------------------------------------------------------------
// t=0 gate kernel: z = xz (permuted layout), c_old = 0.
// ---------------------------------------------------------------------------
__global__ void gate0(const float* __restrict__ z, long long z_str,
                      float* __restrict__ c, float* __restrict__ h,
                      long long h_str, int HWp, int n_img)
{
    int idx = blockIdx.x*256 + threadIdx.x;
    if (idx >= n_img*HWp*16) return;
    int fq = idx & 15;
    int pp = idx >> 4;
    int pix = pp % HWp, img = pp / HWp;
    const float* zb = z + (long long)img*z_str + (long long)pix*256 + fq*16;
    float co[4], ho[4];
    #pragma unroll
    for (int e=0;e<4;e++){
        float4 q = *(const float4*)(zb + e*4);   // (i,f,c,o) of one feature
        float cc = hsg(q.x)*fmaxf(q.z, 0.f);
        co[e] = cc;
        ho[e] = hsg(q.w)*fmaxf(cc, 0.f);
    }
    long long cb = ((long long)img*HWp + pix)*64 + fq*4;
    *(float4*)(c + cb) = *(float4*)co;
    *(float4*)(h + (long long)img*h_str + (long long)pix*64 + fq*4) = *(float4*)ho;
}

// ---------------------------------------------------------------------------
// Conv3D 3x3x3 64->1 SAME + ReLU
// ---------------------------------------------------------------------------
__global__ void conv3d_kernel(const float* __restrict__ h, const float* __restrict__ w,
                              const float* __restrict__ b, float* __restrict__ out)
{
    const int idx = blockIdx.x*256 + threadIdx.x;
    if (idx >= BB*TT*32*32) return;
    const int x = idx & 31, y = (idx >> 5) & 31, t = (idx >> 10) & 15, bb = idx >> 14;
    float acc = __ldg(&b[0]);
    #pragma unroll
    for (int dt=-1; dt<=1; dt++){
        const int ti = t + dt;
        if ((unsigned)ti >= (unsigned)TT) continue;
        #pragma unroll
        for (int dy=-1; dy<=1; dy++){
            const int yi = y + dy;
            if ((unsigned)yi >= 32u) continue;
            #pragma unroll
            for (int dx=-1; dx<=1; dx++){
                const int xi = x + dx;
                if ((unsigned)xi >= 32u) continue;
                const float4* hp = (const float4*)(h + ((((long long)bb*TT+ti)*32+yi)*32+xi)*FF);
                const float4* wp = (const float4*)(w + (((dt+1)*3+(dy+1))*3+(dx+1))*FF);
                #pragma unroll
                for (int c4=0;c4<16;c4++){
                    float4 hv = hp[c4], wv = __ldg(&wp[c4]);
                    acc += hv.x*wv.x + hv.y*wv.y + hv.z*wv.z + hv.w*wv.w;
                }
            }
        }
    }
    out[idx] = fmaxf(acc, 0.f);
}

// ---------------------------------------------------------------------------
// Host
// ---------------------------------------------------------------------------
#define O1K 0
#define O1R 106496
#define O2K 516096
#define O2R 663552
#define O3K 811008
#define O3R 827392

extern "C" void kernel_launch(void* const* d_in, const int* in_sizes, int n_in,
                              void* d_out, int out_size)
{
    const float* x   = (const float*)d_in[0];
    const float* k1  = (const float*)d_in[1];
    const float* rk1 = (const float*)d_in[2];
    const float* b1  = (const float*)d_in[3];
    const float* g1  = (const float*)d_in[4];
    const float* be1 = (const float*)d_in[5];
    const float* k2  = (const float*)d_in[6];
    const float* rk2 = (const float*)d_in[7];
    const float* b2  = (const float*)d_in[8];
    const float* g2  = (const float*)d_in[9];
    const float* be2 = (const float*)d_in[10];
    const float* k3  = (const float*)d_in[11];
    const float* rk3 = (const float*)d_in[12];
    const float* b3  = (const float*)d_in[13];
    const float* w3d = (const float*)d_in[14];
    const float* b3d = (const float*)d_in[15];
    float* out = (float*)d_out;

    float *xz, *ha, *h3, *cc, *pb;
    u32* wb;
    cudaGetSymbolAddress((void**)&xz, g_xz);
    cudaGetSymbolAddress((void**)&ha, g_ha);
    cudaGetSymbolAddress((void**)&h3, g_h3);
    cudaGetSymbolAddress((void**)&cc, g_c);
    cudaGetSymbolAddress((void**)&wb, g_wb32);
    cudaGetSymbolAddress((void**)&pb, g_pb);

    auto* f1i = conv_mma<5,1,16,false,false>;
    auto* f1r = conv_mma<5,1,64,false,true>;
    auto* f2i = conv_mma<3,1,64,true,false>;
    auto* f2r = conv_mma<3,1,64,false,true>;
    auto* f3i = conv_mma<1,2,64,true,false>;
    auto* f3r = conv_mma<1,1,64,false,true>;
    cudaFuncSetAttribute(f1i, cudaFuncAttributeMaxDynamicSharedMemorySize, SMEM_TOT);
    cudaFuncSetAttribute(f1r, cudaFuncAttributeMaxDynamicSharedMemorySize, SMEM_TOT);
    cudaFuncSetAttribute(f2i, cudaFuncAttributeMaxDynamicSharedMemorySize, SMEM_TOT);
    cudaFuncSetAttribute(f2r, cudaFuncAttributeMaxDynamicSharedMemorySize, SMEM_TOT);
    cudaFuncSetAttribute(f3i, cudaFuncAttributeMaxDynamicSharedMemorySize, SMEM_TOT);
    cudaFuncSetAttribute(f3r, cudaFuncAttributeMaxDynamicSharedMemorySize, SMEM_TOT);

    // weight + bias prep (runs every call; trivial cost)
    prep_w<<<208, 256>>>(k1,  wb + O1K, 400,  13);
    prep_w<<<800, 256>>>(rk1, wb + O1R, 1600, 50);
    prep_w<<<288, 256>>>(k2,  wb + O2K, 576,  18);
    prep_w<<<288, 256>>>(rk2, wb + O2R, 576,  18);
    prep_w<<<32,  256>>>(k3,  wb + O3K, 64,   2);
    prep_w<<<32,  256>>>(rk3, wb + O3R, 64,   2);
    prep_bias<<<3, 256>>>(b1, b2, b3, pb);

    const long long X_IMG = (long long)HW*16;
    const long long XZ_IMG = (long long)TT*HW*256, XZ_T = (long long)HW*256;
    const long long H_IMG = (long long)TT*HW*FF,   H_T  = (long long)HW*FF;
    const long long XZ3_IMG = (long long)TT*HW3*256, XZ3_T = (long long)HW3*256;
    const long long H3_IMG = (long long)TT*HW3*FF,   H3_T  = (long long)HW3*FF;

    // ============ Layer 1: ConvLSTM 5x5 ============
    f1i<<<2048, 512, SMEM_TOT>>>(x, X_IMG, wb+O1K, 13, pb,
        nullptr, nullptr, nullptr, 0, nullptr, xz, XZ_T, HH, WW, HH, WW);
    gate0<<<1024, 256>>>(xz, XZ_IMG, cc, ha, H_IMG, HW, BB);
    for (int t = 1; t < TT; t++)
        f1r<<<128, 512, SMEM_TOT>>>(ha + (long long)(t-1)*H_T, H_IMG, wb+O1R, 50,
            nullptr, nullptr, nullptr, xz + (long long)t*XZ_T, XZ_IMG, cc,
            ha + (long long)t*H_T, H_IMG, HH, WW, HH, WW);

    // ============ Layer 2: ConvLSTM 3x3 (BN1 folded into A-gather) ============
    f2i<<<2048, 512, SMEM_TOT>>>(ha, H_T, wb+O2K, 18, pb+256,
        g1, be1, nullptr, 0, nullptr, xz, XZ_T, HH, WW, HH, WW);
    gate0<<<1024, 256>>>(xz, XZ_IMG, cc, ha, H_IMG, HW, BB);
    for (int t = 1; t < TT; t++)
        f2r<<<128, 512, SMEM_TOT>>>(ha + (long long)(t-1)*H_T, H_IMG, wb+O2R, 18,
            nullptr, nullptr, nullptr, xz + (long long)t*XZ_T, XZ_IMG, cc,
            ha + (long long)t*H_T, H_IMG, HH, WW, HH, WW);

    // ============ Layer 3: ConvLSTM 1x1 stride 2 (BN2 folded) ============
    f3i<<<512, 512, SMEM_TOT>>>(ha, H_T, wb+O3K, 2, pb+512,
        g2, be2, nullptr, 0, nullptr, xz, XZ3_T, HH, WW, 32, 32);
    gate0<<<256, 256>>>(xz, XZ3_IMG, cc, h3, H3_IMG, HW3, BB);
    for (int t = 1; t < TT; t++)
        f3r<<<32, 512, SMEM_TOT>>>(h3 + (long long)(t-1)*H3_T, H3_IMG, wb+O3R, 2,
            nullptr, nullptr, nullptr, xz + (long long)t*XZ3_T, XZ3_IMG, cc,
            h3 + (long long)t*H3_T, H3_IMG, 32, 32, 32, 32);

    conv3d_kernel<<<256, 256>>>(h3, w3d, b3d, out);
}